// round 8
// baseline (speedup 1.0000x reference)
#include <cuda_runtime.h>
#include <mma.h>
#include <cstdint>
#include <cstddef>

using namespace nvcuda;

#define SEQL 512
#define NBATCH 64
#define ISZ 256
#define HSZ 1024
#define NGATES 4096
#define NCTA 128
#define NTHR 256
#define BH (NBATCH * HSZ)

// ---------------- device scratch (no allocations allowed) ----------------
__device__ float g_P[(size_t)SEQL * NBATCH * NGATES];  // x-projections, 512MB
__device__ float g_hT[2][HSZ * NBATCH];                // transposed h ping-pong
__device__ unsigned g_count;                           // grid barrier counter

// ---------------- persistent-kernel smem layout (floats) ----------------
// Per-warp: 4 buffers of [16 k][68 floats] = 4*1088 floats (17408 B).
// Weight staging at init reuses the same area (16384 B <= 17408 B).
#define BUF_FLOATS 1088                      // 16*68
#define WARP_STAGE_FLOATS (4 * BUF_FLOATS)   // 4352
#define STAGE_FLOATS (8 * WARP_STAGE_FLOATS) // 34816
#define PS_STRIDE 2304                       // 64*36 padded partials (ldm mult of 4!)
#define PS_FLOATS (8 * PS_STRIDE)            // 18432
#define HST_OFF (STAGE_FLOATS + PS_FLOATS)   // 53248
#define HST_FLOATS (8 * 68)                  // 544
#define SMEM_FLOATS (HST_OFF + HST_FLOATS)   // 53792
#define SMEM_BYTES (SMEM_FLOATS * 4)         // 215168 B

// ---------------- cp.async helpers ----------------
__device__ __forceinline__ void cp16(void* smem_p, const void* gmem) {
    uint32_t s = (uint32_t)__cvta_generic_to_shared(smem_p);
    asm volatile("cp.async.cg.shared.global [%0], [%1], 16;\n" :: "r"(s), "l"(gmem));
}
__device__ __forceinline__ void cp_commit() { asm volatile("cp.async.commit_group;\n"); }
template<int N> __device__ __forceinline__ void cp_wait() {
    asm volatile("cp.async.wait_group %0;\n" :: "n"(N));
}

// sigmoid: safe at both extremes (exp overflow -> 1/(1+inf) -> 0)
__device__ __forceinline__ float fast_sigmoid(float x) {
    return __fdividef(1.f, 1.f + __expf(-x));
}
// tanh = 1 - 2/(e^{2x}+1): saturates to +1 (e=inf) and -1 (e=0), no NaN
__device__ __forceinline__ float fast_tanh(float x) {
    float e = __expf(2.f * x);
    return 1.f - __fdividef(2.f, e + 1.f);
}

// ---------------- phase 1: P = x @ Wx^T (tf32 wmma, padded smem ldm=36) ----------------
#define XA(st, r, c) xsm[(st) * (128 * 36) + (r) * 36 + (c)]
#define XB(st, r, c) xsm[9216 + (st) * (64 * 36) + (r) * 36 + (c)]
#define XPROJ_SMEM ((9216 + 2 * 64 * 36) * 4)   // 55296 B

__global__ void __launch_bounds__(256) xproj_kernel(
    const float* __restrict__ x,
    const float* __restrict__ Wfx, const float* __restrict__ Wix,
    const float* __restrict__ Wgx, const float* __restrict__ Wox)
{
    constexpr int BM = 128, BN = 64, BK = 32;
    extern __shared__ float xsm[];

    const int tid = threadIdx.x;
    // reset grid-barrier counter for the persistent kernel
    if (blockIdx.x == 0 && blockIdx.y == 0 && tid == 0) g_count = 0u;

    const int m0 = blockIdx.x * BM;
    const int n0 = blockIdx.y * BN;

    const int gate = n0 >> 10;
    const float* Wsel = (gate == 0) ? Wfx : (gate == 1) ? Wix : (gate == 2) ? Wgx : Wox;
    const int u0 = n0 & (HSZ - 1);

    const int wid = tid >> 5;
    const int wm = wid & 3;
    const int wn = wid >> 2;

    wmma::fragment<wmma::accumulator, 16, 16, 8, float> acc[2][2];
    #pragma unroll
    for (int i = 0; i < 2; ++i)
        #pragma unroll
        for (int j = 0; j < 2; ++j) wmma::fill_fragment(acc[i][j], 0.f);

    auto load_chunk = [&](int st, int k0) {
        #pragma unroll
        for (int j = 0; j < 4; ++j) {
            int idx = tid + j * 256;
            int r = idx >> 3, c = (idx & 7) * 4;
            cp16(&XA(st, r, c), x + (size_t)(m0 + r) * ISZ + k0 + c);
        }
        #pragma unroll
        for (int j = 0; j < 2; ++j) {
            int idx = tid + j * 256;
            int r = idx >> 3, c = (idx & 7) * 4;
            cp16(&XB(st, r, c), Wsel + (size_t)(u0 + r) * ISZ + k0 + c);
        }
        cp_commit();
    };

    constexpr int NIT = ISZ / BK;
    load_chunk(0, 0);
    for (int kt = 0; kt < NIT; ++kt) {
        int cur = kt & 1;
        if (kt + 1 < NIT) { load_chunk(cur ^ 1, (kt + 1) * BK); cp_wait<1>(); }
        else              { cp_wait<0>(); }
        __syncthreads();
        #pragma unroll
        for (int kk = 0; kk < BK / 8; ++kk) {
            wmma::fragment<wmma::matrix_a, 16, 16, 8, wmma::precision::tf32, wmma::row_major> a[2];
            wmma::fragment<wmma::matrix_b, 16, 16, 8, wmma::precision::tf32, wmma::col_major> bb[2];
            #pragma unroll
            for (int i = 0; i < 2; ++i) {
                wmma::load_matrix_sync(a[i], &XA(cur, wm * 32 + i * 16, kk * 8), 36);
                #pragma unroll
                for (int e = 0; e < a[i].num_elements; ++e)
                    a[i].x[e] = wmma::__float_to_tf32(a[i].x[e]);
            }
            #pragma unroll
            for (int j = 0; j < 2; ++j) {
                wmma::load_matrix_sync(bb[j], &XB(cur, wn * 32 + j * 16, kk * 8), 36);
                #pragma unroll
                for (int e = 0; e < bb[j].num_elements; ++e)
                    bb[j].x[e] = wmma::__float_to_tf32(bb[j].x[e]);
            }
            #pragma unroll
            for (int i = 0; i < 2; ++i)
                #pragma unroll
                for (int j = 0; j < 2; ++j)
                    wmma::mma_sync(acc[i][j], a[i], bb[j], acc[i][j]);
        }
        __syncthreads();
    }
    #pragma unroll
    for (int i = 0; i < 2; ++i)
        #pragma unroll
        for (int j = 0; j < 2; ++j) {
            float* p = g_P + (size_t)(m0 + wm * 32 + i * 16) * NGATES + (n0 + wn * 32 + j * 16);
            wmma::store_matrix_sync(p, acc[i][j], NGATES, wmma::mem_row_major);
        }
}

// ---------------- phase 2: persistent recurrence ----------------
__global__ void __launch_bounds__(NTHR, 1) lstm_persistent(
    float* __restrict__ out,
    const float* __restrict__ Wfh, const float* __restrict__ Wih,
    const float* __restrict__ Wgh, const float* __restrict__ Woh,
    const float* __restrict__ bfx, const float* __restrict__ bfh,
    const float* __restrict__ bix, const float* __restrict__ bih,
    const float* __restrict__ bgx, const float* __restrict__ bgh,
    const float* __restrict__ boxp, const float* __restrict__ boh)
{
    extern __shared__ float smf[];
    float* Ps  = smf + STAGE_FLOATS;   // [8 warps][64][36] partials
    float* hst = smf + HST_OFF;        // [8 u][68] h transpose stage

    const int tid = threadIdx.x;
    const int lane = tid & 31;
    const int w = tid >> 5;
    const int u0 = blockIdx.x * 8;
    const int kbase = w * 128;

    float* buf0 = smf + w * WARP_STAGE_FLOATS;
    float* buf1 = buf0 + BUF_FLOATS;
    float* buf2 = buf1 + BUF_FLOATS;
    float* buf3 = buf2 + BUF_FLOATS;

    // ---- stage my warp's weight slice [32 n][128 k], load B fragments ----
    {
        float* wst = buf0;  // 16384 B <= 17408 B per-warp stage area
        #pragma unroll
        for (int i = 0; i < 32; ++i) {
            int idx = lane + i * 32;
            int n = idx >> 5, c4 = idx & 31;
            int g = n >> 3, ul = n & 7;
            const float* Wg = (g == 0) ? Wfh : (g == 1) ? Wih : (g == 2) ? Wgh : Woh;
            cp16(wst + n * 128 + c4 * 4,
                 Wg + (size_t)(u0 + ul) * HSZ + kbase + c4 * 4);
        }
        cp_commit();
        cp_wait<0>();
        __syncwarp();
    }
    wmma::fragment<wmma::matrix_b, 16, 16, 8, wmma::precision::tf32, wmma::col_major> bfr[2][16];
    #pragma unroll
    for (int nj = 0; nj < 2; ++nj)
        #pragma unroll
        for (int kf = 0; kf < 16; ++kf) {
            wmma::load_matrix_sync(bfr[nj][kf], buf0 + nj * 16 * 128 + kf * 8, 128);
            #pragma unroll
            for (int e = 0; e < bfr[nj][kf].num_elements; ++e)
                bfr[nj][kf].x[e] = wmma::__float_to_tf32(bfr[nj][kf].x[e]);
        }
    __syncthreads();

    // ---- per-thread epilogue state ----
    float bsf[2], bsi[2], bsg[2], bso[2], cc[2], hv[2];
    #pragma unroll
    for (int j = 0; j < 2; ++j) {
        int idx = tid + j * NTHR;
        int u = u0 + (idx & 7);
        bsf[j] = bfx[u] + bfh[u];
        bsi[j] = bix[u] + bih[u];
        bsg[j] = bgx[u] + bgh[u];
        bso[j] = boxp[u] + boh[u];
        cc[j] = 0.f; hv[j] = 0.f;
    }

    #pragma unroll 1
    for (int t = 0; t < SEQL; ++t) {
        // ---- prefetch g_P for this step (hides DRAM latency under GEMM) ----
        float pre[2][4];
        #pragma unroll
        for (int j = 0; j < 2; ++j) {
            int idx = tid + j * NTHR;
            int b = idx >> 3, u = u0 + (idx & 7);
            const float* Pp = g_P + ((size_t)t * NBATCH + b) * NGATES + u;
            pre[j][0] = Pp[0];
            pre[j][1] = Pp[HSZ];
            pre[j][2] = Pp[2 * HSZ];
            pre[j][3] = Pp[3 * HSZ];
        }

        if (t > 0) {
            const float* hsrc = g_hT[(t - 1) & 1];

            auto issue16 = [&](float* dst, int c) {
                const float* src = hsrc + (size_t)(kbase + c * 16) * NBATCH;
                #pragma unroll
                for (int i = 0; i < 8; ++i) {
                    int idx = lane + i * 32;
                    int r = idx >> 4, c4 = idx & 15;
                    cp16(dst + r * 68 + c4 * 4, src + r * NBATCH + c4 * 4);
                }
                cp_commit();
            };

            issue16(buf0, 0); issue16(buf1, 1); issue16(buf2, 2);

            wmma::fragment<wmma::accumulator, 16, 16, 8, float> acc[4][2];
            #pragma unroll
            for (int mi = 0; mi < 4; ++mi)
                #pragma unroll
                for (int nj = 0; nj < 2; ++nj) wmma::fill_fragment(acc[mi][nj], 0.f);

#define GEMM_CHUNK(C, WN)                                                        \
            {                                                                    \
                cp_wait<WN>(); __syncwarp();                                     \
                const float* bp = (((C) & 3) == 0) ? buf0 :                      \
                                  (((C) & 3) == 1) ? buf1 :                      \
                                  (((C) & 3) == 2) ? buf2 : buf3;                \
                _Pragma("unroll")                                                \
                for (int kk2 = 0; kk2 < 2; ++kk2) {                              \
                    const int kg = (C) * 2 + kk2;                                \
                    wmma::fragment<wmma::matrix_a, 16, 16, 8,                    \
                        wmma::precision::tf32, wmma::col_major> am[4];           \
                    _Pragma("unroll")                                            \
                    for (int mi = 0; mi < 4; ++mi) {                             \
                        wmma::load_matrix_sync(am[mi], bp + (kk2 * 8) * 68 + mi * 16, 68); \
                        _Pragma("unroll")                                        \
                        for (int e = 0; e < am[mi].num_elements; ++e)            \
                            am[mi].x[e] = wmma::__float_to_tf32(am[mi].x[e]);    \
                    }                                                            \
                    _Pragma("unroll")                                            \
                    for (int mi = 0; mi < 4; ++mi)                               \
                        _Pragma("unroll")                                        \
                        for (int nj = 0; nj < 2; ++nj)                           \
                            wmma::mma_sync(acc[mi][nj], am[mi], bfr[nj][kg], acc[mi][nj]); \
                }                                                                \
                if ((C) < 5) {                                                   \
                    float* nb = ((((C) + 3) & 3) == 0) ? buf0 :                  \
                                ((((C) + 3) & 3) == 1) ? buf1 :                  \
                                ((((C) + 3) & 3) == 2) ? buf2 : buf3;            \
                    issue16(nb, (C) + 3);                                        \
                }                                                                \
            }
            GEMM_CHUNK(0, 2) GEMM_CHUNK(1, 2) GEMM_CHUNK(2, 2) GEMM_CHUNK(3, 2)
            GEMM_CHUNK(4, 2) GEMM_CHUNK(5, 2) GEMM_CHUNK(6, 1) GEMM_CHUNK(7, 0)
#undef GEMM_CHUNK

            // store padded partials [w][64][36]  (ldm=36: multiple of 4 — legal)
            #pragma unroll
            for (int mi = 0; mi < 4; ++mi)
                #pragma unroll
                for (int nj = 0; nj < 2; ++nj)
                    wmma::store_matrix_sync(Ps + w * PS_STRIDE + (mi * 16) * 36 + nj * 16,
                                            acc[mi][nj], 36, wmma::mem_row_major);
            __syncthreads();
        }

        // ---- fused epilogue (K-reduction merged in) ----
        float* hout = out + (size_t)t * BH;
        #pragma unroll
        for (int j = 0; j < 2; ++j) {
            int idx = tid + j * NTHR;
            int b = idx >> 3, ul = idx & 7, u = u0 + ul;
            float rf = 0.f, ri = 0.f, rg = 0.f, ro = 0.f;
            if (t > 0) {
                const int base = b * 36 + ul;
                #pragma unroll
                for (int p = 0; p < 8; ++p) {
                    const float* q = Ps + p * PS_STRIDE + base;
                    rf += q[0]; ri += q[8]; rg += q[16]; ro += q[24];
                }
            }
            float pf = rf + pre[j][0] + bsf[j];
            float pi = ri + pre[j][1] + bsi[j];
            float pg = rg + pre[j][2] + bsg[j];
            float po = ro + pre[j][3] + bso[j];
            float f  = fast_sigmoid(pf);
            float ii = fast_sigmoid(pi);
            float gg = fast_tanh(pg);
            float oo = fast_sigmoid(po);
            cc[j] = cc[j] * f + ii * gg;
            float h = fast_tanh(cc[j]) * oo;
            hv[j] = h;
            hout[(size_t)b * HSZ + u] = h;
            hst[ul * 68 + b] = h;   // conflict-free padded transpose stage
        }
        __syncthreads();

        // ---- coalesced transposed h write ----
        float* hTout = g_hT[t & 1];
        if (tid < 128) {
            int ul = tid >> 4, c4 = tid & 15;
            float4 v = *(const float4*)(hst + ul * 68 + c4 * 4);
            *(float4*)(hTout + (size_t)(u0 + ul) * NBATCH + c4 * 4) = v;
        }

        // ---- grid barrier (monotonic counter) ----
        __threadfence();
        __syncthreads();
        if (tid == 0) {
            atomicAdd(&g_count, 1u);
            const unsigned tgt = (unsigned)(t + 1) * NCTA;
            while (*(volatile unsigned*)&g_count < tgt) { }
        }
        __syncthreads();
    }

    // ---- final h and c ----
    #pragma unroll
    for (int j = 0; j < 2; ++j) {
        int idx = tid + j * NTHR;
        int b = idx >> 3, u = u0 + (idx & 7);
        out[(size_t)SEQL * BH + (size_t)b * HSZ + u] = hv[j];
        out[(size_t)SEQL * BH + BH + (size_t)b * HSZ + u] = cc[j];
    }
}

extern "C" void kernel_launch(void* const* d_in, const int* in_sizes, int n_in,
                              void* d_out, int out_size) {
    const float* x    = (const float*)d_in[0];
    const float* Wfx  = (const float*)d_in[1];
    const float* bfx  = (const float*)d_in[2];
    const float* Wix  = (const float*)d_in[3];
    const float* bix  = (const float*)d_in[4];
    const float* Wgx  = (const float*)d_in[5];
    const float* bgx  = (const float*)d_in[6];
    const float* Wox  = (const float*)d_in[7];
    const float* boxp = (const float*)d_in[8];
    const float* Wfh  = (const float*)d_in[9];
    const float* bfh  = (const float*)d_in[10];
    const float* Wih  = (const float*)d_in[11];
    const float* bih  = (const float*)d_in[12];
    const float* Wgh  = (const float*)d_in[13];
    const float* bgh  = (const float*)d_in[14];
    const float* Woh  = (const float*)d_in[15];
    const float* boh  = (const float*)d_in[16];
    float* out = (float*)d_out;

    cudaFuncSetAttribute(xproj_kernel,
                         cudaFuncAttributeMaxDynamicSharedMemorySize, XPROJ_SMEM);
    cudaFuncSetAttribute(lstm_persistent,
                         cudaFuncAttributeMaxDynamicSharedMemorySize, SMEM_BYTES);

    dim3 g1((SEQL * NBATCH) / 128, NGATES / 64);
    xproj_kernel<<<g1, 256, XPROJ_SMEM>>>(x, Wfx, Wix, Wgx, Wox);

    lstm_persistent<<<NCTA, NTHR, SMEM_BYTES>>>(out, Wfh, Wih, Wgh, Woh,
                                                bfx, bfh, bix, bih,
                                                bgx, bgh, boxp, boh);
}

// round 9
// speedup vs baseline: 2.0961x; 2.0961x over previous
#include <cuda_runtime.h>
#include <cuda_fp16.h>
#include <mma.h>
#include <cstdint>
#include <cstddef>

using namespace nvcuda;

#define SEQL 512
#define NBATCH 64
#define ISZ 256
#define HSZ 1024
#define NGATES 4096
#define NCTA 128
#define NTHR 256
#define BH (NBATCH * HSZ)

// ---------------- device scratch ----------------
__device__ float g_P[(size_t)SEQL * NBATCH * NGATES];
__device__ __align__(128) __half g_hTh[2][HSZ * NBATCH];  // transposed h, fp16 ping-pong
__device__ unsigned g_count;

// ---------------- smem layout (bytes) ----------------
// stage: 8 warps x 8 bufs x [16 k][72 b] halves (2304 B/buf) = 147456
// Ps:    8 warps x [64][36] fp32 = 73728   @ 147456
// hstH:  [8 u][72 b] halves = 1152         @ 221184
#define BUF_H 1152                    // halves per buf (16*72)
#define WSTG_H (8 * BUF_H)            // 9216 halves per warp
#define PS_OFF 147456
#define PS_STRIDE 2304                // floats (64*36)
#define HST_OFF 221184
#define SMEM_BYTES (HST_OFF + 1152)   // 222336

__device__ __forceinline__ void cp16(void* smem_p, const void* gmem) {
    uint32_t s = (uint32_t)__cvta_generic_to_shared(smem_p);
    asm volatile("cp.async.cg.shared.global [%0], [%1], 16;\n" :: "r"(s), "l"(gmem));
}
__device__ __forceinline__ void cp_commit() { asm volatile("cp.async.commit_group;\n"); }
template<int N> __device__ __forceinline__ void cp_wait() {
    asm volatile("cp.async.wait_group %0;\n" :: "n"(N));
}
__device__ __forceinline__ float fast_sigmoid(float x) {
    return __fdividef(1.f, 1.f + __expf(-x));
}
__device__ __forceinline__ float fast_tanh(float x) {
    float e = __expf(2.f * x);
    return 1.f - __fdividef(2.f, e + 1.f);
}

// ---------------- phase 1: P = x @ Wx^T (tf32 wmma, ldm=36 padded) ----------------
#define XA(st, r, c) xsm[(st) * (128 * 36) + (r) * 36 + (c)]
#define XB(st, r, c) xsm[9216 + (st) * (64 * 36) + (r) * 36 + (c)]
#define XPROJ_SMEM ((9216 + 2 * 64 * 36) * 4)

__global__ void __launch_bounds__(256) xproj_kernel(
    const float* __restrict__ x,
    const float* __restrict__ Wfx, const float* __restrict__ Wix,
    const float* __restrict__ Wgx, const float* __restrict__ Wox)
{
    extern __shared__ float xsm[];
    const int tid = threadIdx.x;
    if (blockIdx.x == 0 && blockIdx.y == 0 && tid == 0) g_count = 0u;

    const int m0 = blockIdx.x * 128;
    const int n0 = blockIdx.y * 64;
    const int gate = n0 >> 10;
    const float* Wsel = (gate == 0) ? Wfx : (gate == 1) ? Wix : (gate == 2) ? Wgx : Wox;
    const int u0 = n0 & (HSZ - 1);
    const int wid = tid >> 5, wm = wid & 3, wn = wid >> 2;

    wmma::fragment<wmma::accumulator, 16, 16, 8, float> acc[2][2];
    #pragma unroll
    for (int i = 0; i < 2; ++i)
        #pragma unroll
        for (int j = 0; j < 2; ++j) wmma::fill_fragment(acc[i][j], 0.f);

    auto load_chunk = [&](int st, int k0) {
        #pragma unroll
        for (int j = 0; j < 4; ++j) {
            int idx = tid + j * 256, r = idx >> 3, c = (idx & 7) * 4;
            cp16(&XA(st, r, c), x + (size_t)(m0 + r) * ISZ + k0 + c);
        }
        #pragma unroll
        for (int j = 0; j < 2; ++j) {
            int idx = tid + j * 256, r = idx >> 3, c = (idx & 7) * 4;
            cp16(&XB(st, r, c), Wsel + (size_t)(u0 + r) * ISZ + k0 + c);
        }
        cp_commit();
    };

    load_chunk(0, 0);
    for (int kt = 0; kt < 8; ++kt) {
        int cur = kt & 1;
        if (kt + 1 < 8) { load_chunk(cur ^ 1, (kt + 1) * 32); cp_wait<1>(); }
        else            { cp_wait<0>(); }
        __syncthreads();
        #pragma unroll
        for (int kk = 0; kk < 4; ++kk) {
            wmma::fragment<wmma::matrix_a, 16, 16, 8, wmma::precision::tf32, wmma::row_major> a[2];
            wmma::fragment<wmma::matrix_b, 16, 16, 8, wmma::precision::tf32, wmma::col_major> bb[2];
            #pragma unroll
            for (int i = 0; i < 2; ++i) {
                wmma::load_matrix_sync(a[i], &XA(cur, wm * 32 + i * 16, kk * 8), 36);
                #pragma unroll
                for (int e = 0; e < a[i].num_elements; ++e)
                    a[i].x[e] = wmma::__float_to_tf32(a[i].x[e]);
            }
            #pragma unroll
            for (int j = 0; j < 2; ++j) {
                wmma::load_matrix_sync(bb[j], &XB(cur, wn * 32 + j * 16, kk * 8), 36);
                #pragma unroll
                for (int e = 0; e < bb[j].num_elements; ++e)
                    bb[j].x[e] = wmma::__float_to_tf32(bb[j].x[e]);
            }
            #pragma unroll
            for (int i = 0; i < 2; ++i)
                #pragma unroll
                for (int j = 0; j < 2; ++j)
                    wmma::mma_sync(acc[i][j], a[i], bb[j], acc[i][j]);
        }
        __syncthreads();
    }
    #pragma unroll
    for (int i = 0; i < 2; ++i)
        #pragma unroll
        for (int j = 0; j < 2; ++j) {
            float* p = g_P + (size_t)(m0 + wm * 32 + i * 16) * NGATES + (n0 + wn * 32 + j * 16);
            wmma::store_matrix_sync(p, acc[i][j], NGATES, wmma::mem_row_major);
        }
}

// ---------------- phase 2: persistent recurrence (fp16 GEMM path) ----------------
__global__ void __launch_bounds__(NTHR, 1) lstm_persistent(
    float* __restrict__ out,
    const float* __restrict__ Wfh, const float* __restrict__ Wih,
    const float* __restrict__ Wgh, const float* __restrict__ Woh,
    const float* __restrict__ bfx, const float* __restrict__ bfh,
    const float* __restrict__ bix, const float* __restrict__ bih,
    const float* __restrict__ bgx, const float* __restrict__ bgh,
    const float* __restrict__ boxp, const float* __restrict__ boh)
{
    extern __shared__ char smem[];
    __half* stage = (__half*)smem;
    float*  Ps    = (float*)(smem + PS_OFF);
    __half* hstH  = (__half*)(smem + HST_OFF);

    const int tid = threadIdx.x, lane = tid & 31, w = tid >> 5;
    const int u0 = blockIdx.x * 8;
    const int kbase = w * 128;
    __half* wstage = stage + w * WSTG_H;

    // ---- stage fp16 weights [32 n][128 k] (ldm=128), load 16 B fragments ----
    #pragma unroll
    for (int i = 0; i < 32; ++i) {
        int idx = lane + i * 32;           // 0..1023 float4s
        int n = idx >> 5, c4 = idx & 31;
        int g = n >> 3, ul = n & 7;
        const float* Wg = (g == 0) ? Wfh : (g == 1) ? Wih : (g == 2) ? Wgh : Woh;
        float4 v = *(const float4*)(Wg + (size_t)(u0 + ul) * HSZ + kbase + c4 * 4);
        *(__half2*)(wstage + n * 128 + c4 * 4)     = __floats2half2_rn(v.x, v.y);
        *(__half2*)(wstage + n * 128 + c4 * 4 + 2) = __floats2half2_rn(v.z, v.w);
    }
    __syncwarp();
    wmma::fragment<wmma::matrix_b, 16, 16, 16, __half, wmma::col_major> bfr[2][8];
    #pragma unroll
    for (int nj = 0; nj < 2; ++nj)
        #pragma unroll
        for (int kf = 0; kf < 8; ++kf)
            wmma::load_matrix_sync(bfr[nj][kf], wstage + nj * 16 * 128 + kf * 16, 128);
    __syncthreads();

    // ---- per-thread epilogue state ----
    float bsf[2], bsi[2], bsg[2], bso[2], cc[2], hv[2];
    #pragma unroll
    for (int j = 0; j < 2; ++j) {
        int idx = tid + j * NTHR;
        int u = u0 + (idx & 7);
        bsf[j] = bfx[u] + bfh[u];
        bsi[j] = bix[u] + bih[u];
        bsg[j] = bgx[u] + bgh[u];
        bso[j] = boxp[u] + boh[u];
        cc[j] = 0.f; hv[j] = 0.f;
    }

    #pragma unroll 1
    for (int t = 0; t < SEQL; ++t) {
        float pre[2][4];
        #pragma unroll
        for (int j = 0; j < 2; ++j) {
            int idx = tid + j * NTHR;
            int b = idx >> 3, u = u0 + (idx & 7);
            const float* Pp = g_P + ((size_t)t * NBATCH + b) * NGATES + u;
            pre[j][0] = Pp[0];       pre[j][1] = Pp[HSZ];
            pre[j][2] = Pp[2 * HSZ]; pre[j][3] = Pp[3 * HSZ];
        }

        if (t > 0) {
            const __half* hsrc = g_hTh[(t - 1) & 1];

            // issue ALL 8 chunks (16 k-rows each) up front
            #pragma unroll
            for (int c = 0; c < 8; ++c) {
                __half* dst = wstage + c * BUF_H;
                const __half* src = hsrc + (size_t)(kbase + c * 16) * NBATCH;
                #pragma unroll
                for (int i = 0; i < 4; ++i) {
                    int idx = lane + i * 32;        // 0..127 (16-B units)
                    int r = idx >> 3, c8 = (idx & 7) * 8;
                    cp16(dst + r * 72 + c8, src + r * NBATCH + c8);
                }
                cp_commit();
            }

            wmma::fragment<wmma::accumulator, 16, 16, 16, float> acc[4][2];
            #pragma unroll
            for (int mi = 0; mi < 4; ++mi)
                #pragma unroll
                for (int nj = 0; nj < 2; ++nj) wmma::fill_fragment(acc[mi][nj], 0.f);

#define GEMM_CHUNK(C, WN)                                                       \
            {                                                                   \
                cp_wait<WN>(); __syncwarp();                                    \
                const __half* bp = wstage + (C) * BUF_H;                        \
                wmma::fragment<wmma::matrix_a, 16, 16, 16, __half,              \
                               wmma::col_major> am[4];                          \
                _Pragma("unroll")                                               \
                for (int mi = 0; mi < 4; ++mi)                                  \
                    wmma::load_matrix_sync(am[mi], bp + mi * 16, 72);           \
                _Pragma("unroll")                                               \
                for (int mi = 0; mi < 4; ++mi) {                                \
                    wmma::mma_sync(acc[mi][0], am[mi], bfr[0][C], acc[mi][0]);  \
                    wmma::mma_sync(acc[mi][1], am[mi], bfr[1][C], acc[mi][1]);  \
                }                                                               \
            }
            GEMM_CHUNK(0, 7) GEMM_CHUNK(1, 6) GEMM_CHUNK(2, 5) GEMM_CHUNK(3, 4)
            GEMM_CHUNK(4, 3) GEMM_CHUNK(5, 2) GEMM_CHUNK(6, 1) GEMM_CHUNK(7, 0)
#undef GEMM_CHUNK

            #pragma unroll
            for (int mi = 0; mi < 4; ++mi)
                #pragma unroll
                for (int nj = 0; nj < 2; ++nj)
                    wmma::store_matrix_sync(Ps + w * PS_STRIDE + (mi * 16) * 36 + nj * 16,
                                            acc[mi][nj], 36, wmma::mem_row_major);
            __syncthreads();
        }

        // ---- fused epilogue (K-reduction over 8 warp partials) ----
        float* hout = out + (size_t)t * BH;
        #pragma unroll
        for (int j = 0; j < 2; ++j) {
            int idx = tid + j * NTHR;
            int b = idx >> 3, ul = idx & 7, u = u0 + ul;
            float rf = 0.f, ri = 0.f, rg = 0.f, ro = 0.f;
            if (t > 0) {
                const int base = b * 36 + ul;
                #pragma unroll
                for (int p = 0; p < 8; ++p) {
                    const float* q = Ps + p * PS_STRIDE + base;
                    rf += q[0]; ri += q[8]; rg += q[16]; ro += q[24];
                }
            }
            float pf = rf + pre[j][0] + bsf[j];
            float pi = ri + pre[j][1] + bsi[j];
            float pg = rg + pre[j][2] + bsg[j];
            float po = ro + pre[j][3] + bso[j];
            float f  = fast_sigmoid(pf);
            float ii = fast_sigmoid(pi);
            float gg = fast_tanh(pg);
            float oo = fast_sigmoid(po);
            cc[j] = cc[j] * f + ii * gg;
            float h = fast_tanh(cc[j]) * oo;
            hv[j] = h;
            hout[(size_t)b * HSZ + u] = h;
            hstH[ul * 72 + b] = __float2half_rn(h);
        }
        __syncthreads();

        // ---- coalesced transposed fp16 h write ----
        __half* hTout = g_hTh[t & 1];
        if (tid < 64) {
            int ul = tid >> 3, c8 = (tid & 7) * 8;
            uint4 v = *(const uint4*)(hstH + ul * 72 + c8);
            *(uint4*)(hTout + (size_t)(u0 + ul) * NBATCH + c8) = v;
        }

        // ---- grid barrier ----
        __threadfence();
        __syncthreads();
        if (tid == 0) {
            atomicAdd(&g_count, 1u);
            const unsigned tgt = (unsigned)(t + 1) * NCTA;
            while (*(volatile unsigned*)&g_count < tgt) { }
        }
        __syncthreads();
    }

    #pragma unroll
    for (int j = 0; j < 2; ++j) {
        int idx = tid + j * NTHR;
        int b = idx >> 3, u = u0 + (idx & 7);
        out[(size_t)SEQL * BH + (size_t)b * HSZ + u] = hv[j];
        out[(size_t)SEQL * BH + BH + (size_t)b * HSZ + u] = cc[j];
    }
}

extern "C" void kernel_launch(void* const* d_in, const int* in_sizes, int n_in,
                              void* d_out, int out_size) {
    const float* x    = (const float*)d_in[0];
    const float* Wfx  = (const float*)d_in[1];
    const float* bfx  = (const float*)d_in[2];
    const float* Wix  = (const float*)d_in[3];
    const float* bix  = (const float*)d_in[4];
    const float* Wgx  = (const float*)d_in[5];
    const float* bgx  = (const float*)d_in[6];
    const float* Wox  = (const float*)d_in[7];
    const float* boxp = (const float*)d_in[8];
    const float* Wfh  = (const float*)d_in[9];
    const float* bfh  = (const float*)d_in[10];
    const float* Wih  = (const float*)d_in[11];
    const float* bih  = (const float*)d_in[12];
    const float* Wgh  = (const float*)d_in[13];
    const float* bgh  = (const float*)d_in[14];
    const float* Woh  = (const float*)d_in[15];
    const float* boh  = (const float*)d_in[16];
    float* out = (float*)d_out;

    cudaFuncSetAttribute(xproj_kernel,
                         cudaFuncAttributeMaxDynamicSharedMemorySize, XPROJ_SMEM);
    cudaFuncSetAttribute(lstm_persistent,
                         cudaFuncAttributeMaxDynamicSharedMemorySize, SMEM_BYTES);

    dim3 g1((SEQL * NBATCH) / 128, NGATES / 64);
    xproj_kernel<<<g1, 256, XPROJ_SMEM>>>(x, Wfx, Wix, Wgx, Wox);

    lstm_persistent<<<NCTA, NTHR, SMEM_BYTES>>>(out, Wfh, Wih, Wgh, Woh,
                                                bfx, bfh, bix, bih,
                                                bgx, bgh, boxp, boh);
}